// round 2
// baseline (speedup 1.0000x reference)
#include <cuda_runtime.h>
#include <cstdint>

// ============================================================================
// SymplecticLeapfrogLayer: fused 3-step leapfrog integrator with NN Hamiltonian
//
// q = x[:,-1,:], p = x[:,-1,:] - x[:,-2,:]
// per step: dH = grad H([q,p]);  p -= 0.5*DT*dH[:,:F]; q += DT*dH[:,F:];
//           dH2 = grad H([q,p]); p -= 0.5*DT*dH2[:,:F]
// grad H: h1=tanh(s@W1+b1); h2=tanh(h1@W2+b2); g2=wout*(1-h2^2);
//         g1=(1-h1^2)*(g2@W2^T); dH = g1@W1^T
//
// Fully fused: one CTA owns 32 samples for the whole trajectory; state (q,p),
// h1, g2 live in SMEM; weights (tf32-rounded, + transposes) stream L2->SMEM
// via cp.async double buffering; GEMM cores use mma.sync m16n8k8 tf32.
// 512 threads / 16 warps: warp tiling 2(M) x 8(N), each warp 16x32 of C.
// ============================================================================

#define B_TOTAL   65536
#define FDIM      128
#define NH        256
#define STEPS     3
#define DT        0.1f
#define M_BLK     32
#define KC        32
#define NCHUNK    (NH / KC)          // 8
#define S_STRIDE  260                // A-tile row stride (conflict-free frag loads)
#define B_STRIDE  264                // B-tile row stride (conflict-free frag loads)
#define THREADS   512
#define SMEM_FLOATS (3*M_BLK*S_STRIDE + 2*KC*B_STRIDE + 3*NH)
#define SMEM_BYTES  (SMEM_FLOATS * 4)

// tf32-rounded weights + explicit transposes (static device scratch: allowed)
__device__ float g_W1r[NH*NH];
__device__ float g_W1T[NH*NH];
__device__ float g_W2r[NH*NH];
__device__ float g_W2T[NH*NH];

__device__ __forceinline__ uint32_t tf32_bits(float x) {
    uint32_t r;
    asm("cvt.rna.tf32.f32 %0, %1;" : "=r"(r) : "f"(x));
    return r;
}

__device__ __forceinline__ void mma8(float* c,
                                     uint32_t a0, uint32_t a1, uint32_t a2, uint32_t a3,
                                     uint32_t b0, uint32_t b1) {
    asm volatile("mma.sync.aligned.m16n8k8.row.col.f32.tf32.tf32.f32 "
                 "{%0,%1,%2,%3}, {%4,%5,%6,%7}, {%8,%9}, {%0,%1,%2,%3};"
                 : "+f"(c[0]), "+f"(c[1]), "+f"(c[2]), "+f"(c[3])
                 : "r"(a0), "r"(a1), "r"(a2), "r"(a3), "r"(b0), "r"(b1));
}

__device__ __forceinline__ void cp16(uint32_t saddr, const void* g) {
    asm volatile("cp.async.cg.shared.global [%0], [%1], 16;" :: "r"(saddr), "l"(g));
}
__device__ __forceinline__ void cp_commit() { asm volatile("cp.async.commit_group;"); }
__device__ __forceinline__ void cp_wait1()  { asm volatile("cp.async.wait_group 1;"); }
__device__ __forceinline__ void cp_wait0()  { asm volatile("cp.async.wait_group 0;"); }

__global__ void prep_kernel(const float* __restrict__ W1, const float* __restrict__ W2) {
    int idx = blockIdx.x * blockDim.x + threadIdx.x;   // 65536 threads, one (k,n) each
    int k = idx >> 8, n = idx & 255;
    (void)k;
    g_W1r[idx] = __uint_as_float(tf32_bits(W1[idx]));
    g_W1T[idx] = __uint_as_float(tf32_bits(W1[n*NH + (idx >> 8)]));
    g_W2r[idx] = __uint_as_float(tf32_bits(W2[idx]));
    g_W2T[idx] = __uint_as_float(tf32_bits(W2[n*NH + (idx >> 8)]));
}

// EPI: 0: h1 = tanh(v+b1)                      -> sOut (=sH1)
//      1: h2 = tanh(v+b2); g2 = wout*(1-h2^2)  -> sOut (=sG2)
//      2: g1 = (1-h1^2)*v  (reads+writes sOut = sH1 in place)
//      3: leapfrog (phase 0): p -= .5*DT*v (n<F); q += DT*v (n>=F)
//      4: leapfrog (phase 1): p -= .5*DT*v (n<F) only
template<int EPI>
__device__ __forceinline__ void gemm256(const float* __restrict__ Bg,
                                        const float* sA, float* sOut,
                                        float* sB, const float* sBias,
                                        const float* swo, float* sS_,
                                        int tid) {
    const int lane = tid & 31;
    const int wid  = tid >> 5;       // 0..15
    const int wm   = wid >> 3;       // 0..1 : M warp tile (16 rows)
    const int wn   = wid & 7;        // 0..7 : N warp tile (32 cols)
    const int la   = lane & 3;       // threadID in group
    const int lb   = lane >> 2;      // groupID
    const int r0   = wm*16 + lb;

    float acc[4][4];
    #pragma unroll
    for (int j = 0; j < 4; j++) {
        acc[j][0] = 0.f; acc[j][1] = 0.f; acc[j][2] = 0.f; acc[j][3] = 0.f;
    }

    uint32_t sBbase = (uint32_t)__cvta_generic_to_shared(sB);

    // prefetch chunk 0 into buffer 0 (32 rows x 64 16B-chunks = 2048 chunks)
    #pragma unroll
    for (int i = 0; i < 4; i++) {
        int ci = i*THREADS + tid;
        int row = ci >> 6, c16 = ci & 63;
        cp16(sBbase + (uint32_t)(row*B_STRIDE + c16*4)*4u, Bg + row*NH + c16*4);
    }
    cp_commit();

    for (int ch = 0; ch < NCHUNK; ch++) {
        const int cb = ch & 1;
        if (ch + 1 < NCHUNK) {
            const float* Bgc = Bg + (ch+1)*KC*NH;
            uint32_t base = sBbase + (uint32_t)((ch+1) & 1) * (KC*B_STRIDE*4u);
            #pragma unroll
            for (int i = 0; i < 4; i++) {
                int ci = i*THREADS + tid;
                int row = ci >> 6, c16 = ci & 63;
                cp16(base + (uint32_t)(row*B_STRIDE + c16*4)*4u, Bgc + row*NH + c16*4);
            }
            cp_commit();
            cp_wait1();
        } else {
            cp_wait0();
        }
        __syncthreads();

        const float* Bs = sB + cb*(KC*B_STRIDE);
        #pragma unroll
        for (int kk = 0; kk < KC/8; kk++) {
            const int acol = ch*KC + kk*8 + la;
            uint32_t a0 = tf32_bits(sA[ r0    *S_STRIDE + acol    ]);
            uint32_t a1 = tf32_bits(sA[(r0+8) *S_STRIDE + acol    ]);
            uint32_t a2 = tf32_bits(sA[ r0    *S_STRIDE + acol + 4]);
            uint32_t a3 = tf32_bits(sA[(r0+8) *S_STRIDE + acol + 4]);
            const float* Bp = Bs + (kk*8 + la)*B_STRIDE + wn*32 + lb;
            #pragma unroll
            for (int j = 0; j < 4; j++) {
                uint32_t b0 = __float_as_uint(Bp[j*8]);
                uint32_t b1 = __float_as_uint(Bp[j*8 + 4*B_STRIDE]);
                mma8(acc[j], a0, a1, a2, a3, b0, b1);
            }
        }
        __syncthreads();
    }

    // epilogue: c-frag rows {r0, r0+8}, cols {2*la, 2*la+1} within each 8-col j-tile
    #pragma unroll
    for (int j = 0; j < 4; j++) {
        const int nbase = wn*32 + j*8 + 2*la;
        #pragma unroll
        for (int half = 0; half < 2; half++) {
            const int r = r0 + half*8;
            #pragma unroll
            for (int cc = 0; cc < 2; cc++) {
                float v = acc[j][half*2 + cc];
                const int nn = nbase + cc;
                if (EPI == 0) {
                    float h = tanhf(v + sBias[nn]);
                    sOut[r*S_STRIDE + nn] = h;
                } else if (EPI == 1) {
                    float h = tanhf(v + sBias[nn]);
                    sOut[r*S_STRIDE + nn] = swo[nn] * (1.f - h*h);
                } else if (EPI == 2) {
                    float h1 = sOut[r*S_STRIDE + nn];
                    sOut[r*S_STRIDE + nn] = (1.f - h1*h1) * v;
                } else {
                    if (nn < FDIM) {
                        sS_[r*S_STRIDE + FDIM + nn] -= 0.5f*DT*v;   // p kick
                    } else if (EPI == 3) {
                        sS_[r*S_STRIDE + (nn - FDIM)] += DT*v;      // q drift
                    }
                }
            }
        }
    }
    __syncthreads();
}

__global__ void __launch_bounds__(THREADS, 1)
leapfrog_kernel(const float* __restrict__ x,
                const float* __restrict__ b1,
                const float* __restrict__ b2,
                const float* __restrict__ wout,
                float* __restrict__ out) {
    extern __shared__ float smem[];
    float* sS  = smem;                        // [32][260] state: q(0:128)|p(128:256)
    float* sH1 = sS  + M_BLK*S_STRIDE;        // [32][260] h1 / g1
    float* sG2 = sH1 + M_BLK*S_STRIDE;        // [32][260] g2
    float* sB  = sG2 + M_BLK*S_STRIDE;        // [2][32][264] weight tiles
    float* sb1 = sB  + 2*KC*B_STRIDE;
    float* sb2 = sb1 + NH;
    float* swo = sb2 + NH;

    const int tid  = threadIdx.x;
    const int base = blockIdx.x * M_BLK;

    if (tid < NH) {
        sb1[tid] = b1[tid];
        sb2[tid] = b2[tid];
        swo[tid] = wout[tid];
    }

    // load state: q = x[b,15,:], p = x[b,15,:] - x[b,14,:]
    #pragma unroll
    for (int i = 0; i < (M_BLK*FDIM)/THREADS; i++) {   // 8 iters
        int idx = i*THREADS + tid;
        int r = idx >> 7, c = idx & 127;
        size_t gb = (size_t)(base + r) * (16*FDIM);
        float a  = x[gb + 15*FDIM + c];
        float bm = x[gb + 14*FDIM + c];
        sS[r*S_STRIDE + c]        = a;
        sS[r*S_STRIDE + FDIM + c] = a - bm;
    }
    __syncthreads();

    for (int step = 0; step < STEPS; step++) {
        for (int phase = 0; phase < 2; phase++) {
            gemm256<0>(g_W1r, sS,  sH1, sB, sb1, swo, sS, tid);  // z1 -> h1
            gemm256<1>(g_W2r, sH1, sG2, sB, sb2, swo, sS, tid);  // z2 -> g2
            gemm256<2>(g_W2T, sG2, sH1, sB, sb1, swo, sS, tid);  // g1 (in place)
            if (phase == 0)
                gemm256<3>(g_W1T, sH1, sS, sB, sb1, swo, sS, tid); // dH -> kick+drift
            else
                gemm256<4>(g_W1T, sH1, sS, sB, sb1, swo, sS, tid); // dH2 -> half kick
        }
    }

    // output: concat(q,p) == sS layout directly
    #pragma unroll
    for (int i = 0; i < (M_BLK*NH)/THREADS; i++) {     // 16 iters
        int idx = i*THREADS + tid;
        int r = idx >> 8, c = idx & 255;
        out[(size_t)(base + r)*NH + c] = sS[r*S_STRIDE + c];
    }
}

extern "C" void kernel_launch(void* const* d_in, const int* in_sizes, int n_in,
                              void* d_out, int out_size) {
    const float* x    = (const float*)d_in[0];
    const float* W1   = (const float*)d_in[1];
    const float* b1   = (const float*)d_in[2];
    const float* W2   = (const float*)d_in[3];
    const float* b2   = (const float*)d_in[4];
    const float* Wout = (const float*)d_in[5];
    float* out = (float*)d_out;

    cudaFuncSetAttribute(leapfrog_kernel,
                         cudaFuncAttributeMaxDynamicSharedMemorySize, SMEM_BYTES);

    prep_kernel<<<NH, NH>>>(W1, W2);
    leapfrog_kernel<<<B_TOTAL/M_BLK, THREADS, SMEM_BYTES>>>(x, b1, b2, Wout, out);
}

// round 3
// speedup vs baseline: 1.6288x; 1.6288x over previous
#include <cuda_runtime.h>
#include <cuda_bf16.h>
#include <cstdint>

// ============================================================================
// SymplecticLeapfrogLayer: fused 3-step leapfrog integrator with NN Hamiltonian
//
// q = x[:,-1,:], p = x[:,-1,:] - x[:,-2,:]
// per step: dH = grad H([q,p]);  p -= 0.5*DT*dH[:,:F]; q += DT*dH[:,F:];
//           dH2 = grad H([q,p]); p -= 0.5*DT*dH2[:,:F]
// grad H: h1=tanh(s@W1+b1); h2=tanh(h1@W2+b2); g2=wout*(1-h2^2);
//         g1=(1-h1^2)*(g2@W2^T); dH = g1@W1^T
//
// bf16 m16n8k16 MMA cores. One CTA owns 32 samples for the whole trajectory.
// fp32 state + fp32 h1 (for the sensitive (1-h1^2) factor) in SMEM; bf16
// mirrors of all MMA A-operands; bf16 weights (pre-transposed to [n][k],
// k-contiguous) stream L2->SMEM via cp.async double buffering (KC=64).
// Every fragment register is a single 32-bit LDS of a bf16x2 pair.
// ============================================================================

#define B_TOTAL   65536
#define FDIM      128
#define NH        256
#define STEPS     3
#define DT        0.1f
#define M_BLK     32
#define KC        64
#define NCHUNK    (NH / KC)          // 4
#define SF        260                // fp32 activation row stride (elements)
#define SAB       264                // bf16 activation row stride (elems, ==8 mod 64)
#define BS2       72                 // bf16 weight tile row stride (elems, 144B/row)
#define THREADS   512
#define SMEM_BYTES (2*M_BLK*SF*4 + 3*M_BLK*SAB*2 + 2*NH*BS2*2 + 3*NH*4)

// bf16 weights in [n][k] layout (k contiguous). Note: [n][k] image of W is
// W^T row-major, so: g_W1b = operand W1, g_W1Tb = operand W1^T, etc.
__device__ __nv_bfloat16 g_W1b [NH*NH];
__device__ __nv_bfloat16 g_W1Tb[NH*NH];
__device__ __nv_bfloat16 g_W2b [NH*NH];
__device__ __nv_bfloat16 g_W2Tb[NH*NH];

__device__ __forceinline__ uint32_t ld32(const __nv_bfloat16* p) {
    return *(const uint32_t*)p;
}
__device__ __forceinline__ uint32_t pack_bf2(float lo, float hi) {
    uint32_t r;
    asm("cvt.rn.bf16x2.f32 %0, %1, %2;" : "=r"(r) : "f"(hi), "f"(lo));
    return r;
}

__device__ __forceinline__ void mma16(float* c,
                                      uint32_t a0, uint32_t a1, uint32_t a2, uint32_t a3,
                                      uint32_t b0, uint32_t b1) {
    asm volatile("mma.sync.aligned.m16n8k16.row.col.f32.bf16.bf16.f32 "
                 "{%0,%1,%2,%3}, {%4,%5,%6,%7}, {%8,%9}, {%0,%1,%2,%3};"
                 : "+f"(c[0]), "+f"(c[1]), "+f"(c[2]), "+f"(c[3])
                 : "r"(a0), "r"(a1), "r"(a2), "r"(a3), "r"(b0), "r"(b1));
}

__device__ __forceinline__ void cp16(uint32_t saddr, const void* g) {
    asm volatile("cp.async.cg.shared.global [%0], [%1], 16;" :: "r"(saddr), "l"(g));
}
__device__ __forceinline__ void cp_commit() { asm volatile("cp.async.commit_group;"); }
__device__ __forceinline__ void cp_wait1()  { asm volatile("cp.async.wait_group 1;"); }
__device__ __forceinline__ void cp_wait0()  { asm volatile("cp.async.wait_group 0;"); }

__global__ void prep_kernel(const float* __restrict__ W1, const float* __restrict__ W2) {
    int idx = blockIdx.x * blockDim.x + threadIdx.x;   // idx = n*256 + k
    int n = idx >> 8, k = idx & 255;
    g_W1Tb[idx] = __float2bfloat16(W1[idx]);           // W1^T operand == W1 row-major
    g_W2Tb[idx] = __float2bfloat16(W2[idx]);
    g_W1b [idx] = __float2bfloat16(W1[k*NH + n]);      // W1 operand == W1^T row-major
    g_W2b [idx] = __float2bfloat16(W2[k*NH + n]);
}

// EPI: 0: h1 = tanh(v+b1)                      -> outF (fp32) + outB (bf16)
//      1: h2 = tanh(v+b2); g2 = wout*(1-h2^2)  -> outB (bf16)
//      2: g1 = (1-h1f^2)*v  (reads outF=sH1f)  -> outB (bf16, = sH1b)
//      3: leapfrog (phase 0): p -= .5*DT*v (n<F); q += DT*v (n>=F)  [+ bf16 mirror]
//      4: leapfrog (phase 1): p -= .5*DT*v (n<F) only               [+ bf16 mirror]
template<int EPI>
__device__ __forceinline__ void gemm256(const __nv_bfloat16* __restrict__ Bg,
                                        const __nv_bfloat16* sA,
                                        __nv_bfloat16* outB, float* outF,
                                        __nv_bfloat16* sBw,
                                        const float* sBias, const float* swo,
                                        float* sS, __nv_bfloat16* sSb, int tid) {
    const int lane = tid & 31;
    const int wid  = tid >> 5;       // 0..15
    const int wm   = wid >> 3;       // 0..1 : M warp tile (16 rows)
    const int wn   = wid & 7;        // 0..7 : N warp tile (32 cols)
    const int la   = lane & 3;       // threadID in group
    const int lb   = lane >> 2;      // groupID
    const int r0   = wm*16 + lb;

    float acc[4][4];
    #pragma unroll
    for (int j = 0; j < 4; j++) {
        acc[j][0] = 0.f; acc[j][1] = 0.f; acc[j][2] = 0.f; acc[j][3] = 0.f;
    }

    uint32_t sBbase = (uint32_t)__cvta_generic_to_shared(sBw);

    // prefetch chunk 0 into buffer 0: 256 rows(n) x 128B(k) = 2048 x 16B
    #pragma unroll
    for (int i = 0; i < 4; i++) {
        int ci = i*THREADS + tid;
        int row = ci >> 3, c16 = ci & 7;
        cp16(sBbase + (uint32_t)(row*144 + c16*16), Bg + row*NH + c16*8);
    }
    cp_commit();

    for (int ch = 0; ch < NCHUNK; ch++) {
        const int cb = ch & 1;
        if (ch + 1 < NCHUNK) {
            const __nv_bfloat16* Bgc = Bg + (ch+1)*KC;
            uint32_t base = sBbase + (uint32_t)((ch+1) & 1) * (NH*BS2*2);
            #pragma unroll
            for (int i = 0; i < 4; i++) {
                int ci = i*THREADS + tid;
                int row = ci >> 3, c16 = ci & 7;
                cp16(base + (uint32_t)(row*144 + c16*16), Bgc + row*NH + c16*8);
            }
            cp_commit();
            cp_wait1();
        } else {
            cp_wait0();
        }
        __syncthreads();

        const __nv_bfloat16* Bs = sBw + cb*(NH*BS2);
        #pragma unroll
        for (int s = 0; s < 4; s++) {                  // 4 k16-steps per chunk
            const int c = ch*KC + s*16 + 2*la;
            uint32_t a0 = ld32(sA +  r0   *SAB + c);
            uint32_t a1 = ld32(sA + (r0+8)*SAB + c);
            uint32_t a2 = ld32(sA +  r0   *SAB + c + 8);
            uint32_t a3 = ld32(sA + (r0+8)*SAB + c + 8);
            const __nv_bfloat16* Bp = Bs + (wn*32 + lb)*BS2 + s*16 + 2*la;
            #pragma unroll
            for (int j = 0; j < 4; j++) {
                uint32_t b0 = ld32(Bp + j*8*BS2);
                uint32_t b1 = ld32(Bp + j*8*BS2 + 8);
                mma16(acc[j], a0, a1, a2, a3, b0, b1);
            }
        }
        __syncthreads();
    }

    // epilogue: c-frag rows {r0, r0+8}, col pairs {2la, 2la+1} per 8-col j-tile
    #pragma unroll
    for (int j = 0; j < 4; j++) {
        const int n0 = wn*32 + j*8 + 2*la;
        #pragma unroll
        for (int half = 0; half < 2; half++) {
            const int r = r0 + half*8;
            float v0 = acc[j][half*2 + 0];
            float v1 = acc[j][half*2 + 1];
            if (EPI == 0) {
                float h0 = tanhf(v0 + sBias[n0]);
                float h1 = tanhf(v1 + sBias[n0+1]);
                outF[r*SF + n0]     = h0;
                outF[r*SF + n0 + 1] = h1;
                *(uint32_t*)&outB[r*SAB + n0] = pack_bf2(h0, h1);
            } else if (EPI == 1) {
                float h0 = tanhf(v0 + sBias[n0]);
                float h1 = tanhf(v1 + sBias[n0+1]);
                float g0 = swo[n0]   * (1.f - h0*h0);
                float g1 = swo[n0+1] * (1.f - h1*h1);
                *(uint32_t*)&outB[r*SAB + n0] = pack_bf2(g0, g1);
            } else if (EPI == 2) {
                float h0 = outF[r*SF + n0];
                float h1 = outF[r*SF + n0 + 1];
                float g0 = (1.f - h0*h0) * v0;
                float g1 = (1.f - h1*h1) * v1;
                *(uint32_t*)&outB[r*SAB + n0] = pack_bf2(g0, g1);
            } else {
                if (n0 < FDIM) {                        // p half-kick
                    float p0 = sS[r*SF + FDIM + n0]     - 0.5f*DT*v0;
                    float p1 = sS[r*SF + FDIM + n0 + 1] - 0.5f*DT*v1;
                    sS[r*SF + FDIM + n0]     = p0;
                    sS[r*SF + FDIM + n0 + 1] = p1;
                    *(uint32_t*)&sSb[r*SAB + FDIM + n0] = pack_bf2(p0, p1);
                } else if (EPI == 3) {                  // q drift
                    const int cq = n0 - FDIM;
                    float q0 = sS[r*SF + cq]     + DT*v0;
                    float q1 = sS[r*SF + cq + 1] + DT*v1;
                    sS[r*SF + cq]     = q0;
                    sS[r*SF + cq + 1] = q1;
                    *(uint32_t*)&sSb[r*SAB + cq] = pack_bf2(q0, q1);
                }
            }
        }
    }
    __syncthreads();
}

__global__ void __launch_bounds__(THREADS, 1)
leapfrog_kernel(const float* __restrict__ x,
                const float* __restrict__ b1,
                const float* __restrict__ b2,
                const float* __restrict__ wout,
                float* __restrict__ out) {
    extern __shared__ float smem[];
    float* sS   = smem;                                  // [32][260] fp32 state q|p
    float* sH1f = sS + M_BLK*SF;                         // [32][260] fp32 h1
    __nv_bfloat16* sSb  = (__nv_bfloat16*)(sH1f + M_BLK*SF);  // [32][264] bf16 state
    __nv_bfloat16* sH1b = sSb  + M_BLK*SAB;              // [32][264] bf16 h1 / g1
    __nv_bfloat16* sG2b = sH1b + M_BLK*SAB;              // [32][264] bf16 g2
    __nv_bfloat16* sBw  = sG2b + M_BLK*SAB;              // [2][256][72] weight tiles
    float* sb1 = (float*)(sBw + 2*NH*BS2);
    float* sb2 = sb1 + NH;
    float* swo = sb2 + NH;

    const int tid  = threadIdx.x;
    const int base = blockIdx.x * M_BLK;

    if (tid < NH) {
        sb1[tid] = b1[tid];
        sb2[tid] = b2[tid];
        swo[tid] = wout[tid];
    }

    // load state: q = x[b,15,:], p = x[b,15,:] - x[b,14,:] (+ bf16 mirror)
    #pragma unroll
    for (int i = 0; i < (M_BLK*FDIM)/THREADS; i++) {     // 8 iters
        int idx = i*THREADS + tid;
        int r = idx >> 7, c = idx & 127;
        size_t gb = (size_t)(base + r) * (16*FDIM);
        float a  = x[gb + 15*FDIM + c];
        float bm = x[gb + 14*FDIM + c];
        float p  = a - bm;
        sS[r*SF + c]        = a;
        sS[r*SF + FDIM + c] = p;
        sSb[r*SAB + c]        = __float2bfloat16(a);
        sSb[r*SAB + FDIM + c] = __float2bfloat16(p);
    }
    __syncthreads();

    for (int step = 0; step < STEPS; step++) {
        for (int phase = 0; phase < 2; phase++) {
            gemm256<0>(g_W1b,  sSb,  sH1b, sH1f, sBw, sb1, swo, sS, sSb, tid); // h1
            gemm256<1>(g_W2b,  sH1b, sG2b, sH1f, sBw, sb2, swo, sS, sSb, tid); // g2
            gemm256<2>(g_W2Tb, sG2b, sH1b, sH1f, sBw, sb1, swo, sS, sSb, tid); // g1
            if (phase == 0)
                gemm256<3>(g_W1Tb, sH1b, sH1b, sH1f, sBw, sb1, swo, sS, sSb, tid);
            else
                gemm256<4>(g_W1Tb, sH1b, sH1b, sH1f, sBw, sb1, swo, sS, sSb, tid);
        }
    }

    // output: concat(q,p) == fp32 sS layout directly
    #pragma unroll
    for (int i = 0; i < (M_BLK*NH)/THREADS; i++) {       // 16 iters
        int idx = i*THREADS + tid;
        int r = idx >> 8, c = idx & 255;
        out[(size_t)(base + r)*NH + c] = sS[r*SF + c];
    }
}

extern "C" void kernel_launch(void* const* d_in, const int* in_sizes, int n_in,
                              void* d_out, int out_size) {
    const float* x    = (const float*)d_in[0];
    const float* W1   = (const float*)d_in[1];
    const float* b1   = (const float*)d_in[2];
    const float* W2   = (const float*)d_in[3];
    const float* b2   = (const float*)d_in[4];
    const float* Wout = (const float*)d_in[5];
    float* out = (float*)d_out;

    cudaFuncSetAttribute(leapfrog_kernel,
                         cudaFuncAttributeMaxDynamicSharedMemorySize, SMEM_BYTES);

    prep_kernel<<<NH, NH>>>(W1, W2);
    leapfrog_kernel<<<B_TOTAL/M_BLK, THREADS, SMEM_BYTES>>>(x, b1, b2, Wout, out);
}